// round 2
// baseline (speedup 1.0000x reference)
#include <cuda_runtime.h>
#include <math.h>
#include <float.h>

#define NB 32
#define NS 32768
#define NF 128
#define DM 128

// ------------------------- scratch (device globals) -------------------------
__device__ float g_chunk[NB * NF * DM];   // pooled half-window sums (already /512)
__device__ float g_h[NB * NF * DM];
__device__ float g_qkv[NB * NF * 384];
__device__ float g_attno[NB * NF * DM];
__device__ float g_tmp[NB * NF * DM];
__device__ float g_ff[NB * NF * DM];
__device__ int   g_topidx[NB * 16];
__device__ float g_topval[NB * 16];

typedef unsigned long long ull;

__device__ __forceinline__ ull pack2(float lo, float hi) {
    ull r; asm("mov.b64 %0, {%1, %2};" : "=l"(r) : "f"(lo), "f"(hi)); return r;
}
__device__ __forceinline__ void unpack2(ull v, float& lo, float& hi) {
    asm("mov.b64 {%0, %1}, %2;" : "=f"(lo), "=f"(hi) : "l"(v));
}
__device__ __forceinline__ ull fma2(ull a, ull b, ull c) {
    ull d; asm("fma.rn.f32x2 %0, %1, %2, %3;" : "=l"(d) : "l"(a), "l"(b), "l"(c)); return d;
}

// ---------------- conv + |.| + pooled half-window sums ----------------------
// y[b,c,t] = sum_{k=0}^{511} x[b, t-256+k] * fb[c,k]   (zero-padded x)
// g_chunk[b,h,c] = (1/512) * sum_{t in [256h, 256h+256)} |y[b,c,t]|
// frame f = chunk[f-1] + chunk[f]  (chunk[-1] = 0)
#define CONV_SMEM (3072 + 65536)

__global__ __launch_bounds__(256, 1) void conv_pool_kernel(const float* __restrict__ x,
                                                           const float* __restrict__ fb)
{
    extern __shared__ __align__(16) float smem[];
    float* xs  = smem;                  // 768 floats: x[t0-256 .. t0+511]
    ull*   ws2 = (ull*)(smem + 768);    // 16 channel-pairs x 512 keys, packed float2

    const int h = blockIdx.x, cg = blockIdx.y, b = blockIdx.z;
    const int tid = threadIdx.x;
    const int t0 = h << 8, c0 = cg << 5;
    const float* xb = x + (size_t)b * NS;

    for (int i = tid; i < 768; i += 256) {
        int g = t0 - 256 + i;
        xs[i] = (g >= 0 && g < NS) ? xb[g] : 0.f;
    }
    for (int idx = tid; idx < 16 * 512; idx += 256) {
        int p = idx >> 9, k = idx & 511;
        int c = c0 + (p << 1);
        ws2[idx] = pack2(fb[c * 512 + k], fb[(c + 1) * 512 + k]);
    }
    __syncthreads();

    const int tt = tid & 31, ct = tid >> 5;   // tt: time lane, ct: channel quad
    ull acc0[8], acc1[8];
#pragma unroll
    for (int u = 0; u < 8; u++) { acc0[u] = 0ull; acc1[u] = 0ull; }

    const float4* xs4 = (const float4*)xs;
    const ull* w2a = ws2 + (size_t)(ct << 1) * 512;
    const ull* w2b = ws2 + (size_t)((ct << 1) + 1) * 512;

    for (int k8 = 0; k8 < 512; k8 += 8) {
        float xr[16];
#pragma unroll
        for (int q = 0; q < 4; q++) {
            float4 v = xs4[(tt << 1) + (k8 >> 2) + q];
            xr[4 * q + 0] = v.x; xr[4 * q + 1] = v.y;
            xr[4 * q + 2] = v.z; xr[4 * q + 3] = v.w;
        }
        ull xp[15];
#pragma unroll
        for (int j = 0; j < 15; j++) xp[j] = pack2(xr[j], xr[j]);
#pragma unroll
        for (int kk = 0; kk < 8; kk++) {
            ull w0 = w2a[k8 + kk];
            ull w1 = w2b[k8 + kk];
#pragma unroll
            for (int u = 0; u < 8; u++) {
                acc0[u] = fma2(xp[kk + u], w0, acc0[u]);
                acc1[u] = fma2(xp[kk + u], w1, acc1[u]);
            }
        }
    }

    float s[4] = {0.f, 0.f, 0.f, 0.f};
#pragma unroll
    for (int u = 0; u < 8; u++) {
        float lo, hi;
        unpack2(acc0[u], lo, hi); s[0] += fabsf(lo); s[1] += fabsf(hi);
        unpack2(acc1[u], lo, hi); s[2] += fabsf(lo); s[3] += fabsf(hi);
    }
#pragma unroll
    for (int c = 0; c < 4; c++) {
        float v = s[c];
#pragma unroll
        for (int o = 16; o; o >>= 1) v += __shfl_xor_sync(0xffffffffu, v, o);
        if (tt == 0) {
            int ch = c0 + (ct << 2) + c;
            g_chunk[((size_t)b * NF + h) * DM + ch] = v * (1.f / 512.f);
        }
    }
}

// ---------------- frames + pos-encoding + embed -----------------------------
__global__ __launch_bounds__(128) void embed_kernel(const float* __restrict__ ew,
                                                    const float* __restrict__ eb)
{
    const int row = blockIdx.x;         // b*128 + t
    const int t = row & 127;
    const int tid = threadIdx.x;
    __shared__ float vec[161];
    {
        float f = g_chunk[(size_t)row * DM + tid];
        if (t > 0) f += g_chunk[(size_t)(row - 1) * DM + tid];
        vec[tid] = f;
    }
    if (tid < 33) {
        // jnp.linspace(-1,1,128): start + iota*delta in f32, endpoint forced to 1.0
        float pos = (t == 127) ? 1.0f
                               : __fadd_rn(-1.0f, __fmul_rn((float)t, __fdiv_rn(2.0f, 127.0f)));
        float v;
        if (tid == 0) v = pos;
        else {
            int k = (tid <= 16) ? (tid - 1) : (tid - 17);
            float fr = __fmul_rn(exp2f((float)k), 3.14159274101257324f);
            float prod = __fmul_rn(pos, fr);
            v = (tid <= 16) ? (float)sin((double)prod) : (float)cos((double)prod);
        }
        vec[128 + tid] = v;
    }
    __syncthreads();
    float a = eb[tid];
    const float* w = ew + (size_t)tid * 161;
    for (int j = 0; j < 161; j++) a = fmaf(vec[j], w[j], a);
    g_h[(size_t)row * DM + tid] = a;
}

// ---------------- generic row-blocked linear (K = 128) ----------------------
template <int NO, bool RELU>
__global__ __launch_bounds__(128) void linear_kernel(const float* __restrict__ in,
                                                     const float* __restrict__ W,
                                                     const float* __restrict__ bias,
                                                     float* __restrict__ out)
{
    const int row0 = blockIdx.x << 3;
    const int tid = threadIdx.x;
    __shared__ __align__(16) float sv[8 * DM];
#pragma unroll
    for (int r = 0; r < 8; r++) sv[r * DM + tid] = in[(size_t)(row0 + r) * DM + tid];
    __syncthreads();

    float acc[NO][8];
#pragma unroll
    for (int o = 0; o < NO; o++) {
        float bv = bias[o * DM + tid];
#pragma unroll
        for (int r = 0; r < 8; r++) acc[o][r] = bv;
    }
    const float4* sv4 = (const float4*)sv;
    const float4* W4 = (const float4*)W;
    for (int j4 = 0; j4 < 32; j4++) {
        float4 wv[NO];
#pragma unroll
        for (int o = 0; o < NO; o++) wv[o] = W4[(size_t)(o * DM + tid) * 32 + j4];
#pragma unroll
        for (int r = 0; r < 8; r++) {
            float4 xv = sv4[r * 32 + j4];
#pragma unroll
            for (int o = 0; o < NO; o++) {
                acc[o][r] = fmaf(wv[o].x, xv.x, acc[o][r]);
                acc[o][r] = fmaf(wv[o].y, xv.y, acc[o][r]);
                acc[o][r] = fmaf(wv[o].z, xv.z, acc[o][r]);
                acc[o][r] = fmaf(wv[o].w, xv.w, acc[o][r]);
            }
        }
    }
#pragma unroll
    for (int r = 0; r < 8; r++)
#pragma unroll
        for (int o = 0; o < NO; o++) {
            float v = acc[o][r];
            if (RELU) v = fmaxf(v, 0.f);
            out[(size_t)(row0 + r) * (NO * DM) + o * DM + tid] = v;
        }
}

// ---------------- attention (one block per (head, batch)) -------------------
__global__ __launch_bounds__(128) void attn_kernel()
{
    const int hd = blockIdx.x, b = blockIdx.y;
    const int tid = threadIdx.x;
    __shared__ __align__(16) float ks[NF * 32];
    __shared__ __align__(16) float vs[NF * 32];
    const float* base = g_qkv + (size_t)b * NF * 384;

    for (int idx = tid; idx < NF * 32; idx += 128) {
        int j = idx >> 5, i = idx & 31;
        ks[idx] = base[j * 384 + 128 + hd * 32 + i];
        vs[idx] = base[j * 384 + 256 + hd * 32 + i];
    }
    float q[32];
    {
        const float4* qp = (const float4*)(base + (size_t)tid * 384 + hd * 32);
#pragma unroll
        for (int i = 0; i < 8; i++) {
            float4 v = qp[i];
            q[4 * i] = v.x; q[4 * i + 1] = v.y; q[4 * i + 2] = v.z; q[4 * i + 3] = v.w;
        }
    }
    __syncthreads();

    float o[32];
#pragma unroll
    for (int i = 0; i < 32; i++) o[i] = 0.f;
    float m = -FLT_MAX, l = 0.f;
    const float scale = 0.17677669529663689f;  // 1/sqrt(32)

    for (int j = 0; j < NF; j++) {
        const float4* kp = (const float4*)(ks + j * 32);
        float s = 0.f;
#pragma unroll
        for (int i = 0; i < 8; i++) {
            float4 kv = kp[i];
            s = fmaf(q[4 * i], kv.x, s); s = fmaf(q[4 * i + 1], kv.y, s);
            s = fmaf(q[4 * i + 2], kv.z, s); s = fmaf(q[4 * i + 3], kv.w, s);
        }
        s *= scale;
        float mn = fmaxf(m, s);
        float c = expf(m - mn);
        float p = expf(s - mn);
        l = l * c + p;
        const float4* vp = (const float4*)(vs + j * 32);
#pragma unroll
        for (int i = 0; i < 8; i++) {
            float4 vv = vp[i];
            o[4 * i]     = o[4 * i] * c + p * vv.x;
            o[4 * i + 1] = o[4 * i + 1] * c + p * vv.y;
            o[4 * i + 2] = o[4 * i + 2] * c + p * vv.z;
            o[4 * i + 3] = o[4 * i + 3] * c + p * vv.w;
        }
        m = mn;
    }
    float inv = 1.f / l;
    float* dst = g_attno + (size_t)(b * NF + tid) * DM + hd * 32;
#pragma unroll
    for (int i = 0; i < 32; i++) dst[i] = o[i] * inv;
}

// ---------------- residual add + layernorm ----------------------------------
__global__ __launch_bounds__(128) void addln_kernel(float* __restrict__ hbuf,
                                                    const float* __restrict__ tbuf,
                                                    const float* __restrict__ w,
                                                    const float* __restrict__ bias)
{
    const int row = blockIdx.x, tid = threadIdx.x;
    __shared__ float sb[4];
    float v = hbuf[(size_t)row * DM + tid] + tbuf[(size_t)row * DM + tid];
    float s = v;
#pragma unroll
    for (int o = 16; o; o >>= 1) s += __shfl_xor_sync(0xffffffffu, s, o);
    if ((tid & 31) == 0) sb[tid >> 5] = s;
    __syncthreads();
    float mean = (sb[0] + sb[1] + sb[2] + sb[3]) * 0.0078125f;
    float dv = v - mean;
    float s2 = dv * dv;
#pragma unroll
    for (int o = 16; o; o >>= 1) s2 += __shfl_xor_sync(0xffffffffu, s2, o);
    __syncthreads();
    if ((tid & 31) == 0) sb[tid >> 5] = s2;
    __syncthreads();
    float var = (sb[0] + sb[1] + sb[2] + sb[3]) * 0.0078125f;
    float r = 1.f / sqrtf(var + 1e-5f);
    hbuf[(size_t)row * DM + tid] = dv * r * w[tid] + bias[tid];
}

// ---------------- attention scores + top-16 ---------------------------------
__global__ __launch_bounds__(128) void topk_kernel(const float* __restrict__ attn_w,
                                                   const float* __restrict__ attn_b)
{
    const int b = blockIdx.x, tid = threadIdx.x;
    __shared__ float sv[128];
    __shared__ float rv[128];
    __shared__ int ri[128];
    const float4* hp = (const float4*)(g_h + (size_t)(b * NF + tid) * DM);
    const float4* wp = (const float4*)attn_w;
    float s = attn_b[0];
#pragma unroll
    for (int i = 0; i < 32; i++) {
        float4 h4 = hp[i], w4 = wp[i];
        s = fmaf(h4.x, w4.x, s); s = fmaf(h4.y, w4.y, s);
        s = fmaf(h4.z, w4.z, s); s = fmaf(h4.w, w4.w, s);
    }
    sv[tid] = s;
    __syncthreads();
    for (int r = 0; r < 16; r++) {
        rv[tid] = sv[tid]; ri[tid] = tid;
        __syncthreads();
        for (int off = 64; off; off >>= 1) {
            if (tid < off) {
                float v2 = rv[tid + off]; int i2 = ri[tid + off];
                if (v2 > rv[tid] || (v2 == rv[tid] && i2 < ri[tid])) { rv[tid] = v2; ri[tid] = i2; }
            }
            __syncthreads();
        }
        if (tid == 0) {
            g_topidx[b * 16 + r] = ri[0];
            g_topval[b * 16 + r] = rv[0];
            sv[ri[0]] = -FLT_MAX;
        }
        __syncthreads();
    }
}

// ---------------- head: amp, pos/atom argmax, scatter -----------------------
__global__ __launch_bounds__(128) void scatter_kernel(const float* __restrict__ amp_w,
                                                      const float* __restrict__ amp_b,
                                                      const float* __restrict__ pos_w,
                                                      const float* __restrict__ pos_b,
                                                      const float* __restrict__ atom_w,
                                                      const float* __restrict__ atom_b,
                                                      const float* __restrict__ dmat,
                                                      float* __restrict__ out)
{
    const int rk = blockIdx.x, b = blockIdx.y, tid = threadIdx.x;
    __shared__ __align__(16) float vec[128];
    __shared__ float rv[128];
    __shared__ int ri[128];
    __shared__ float amp_s;
    __shared__ int jstar_s, astar_s;

    int id = g_topidx[b * 16 + rk];
    float val = g_topval[b * 16 + rk];
    vec[tid] = g_h[(size_t)(b * NF + id) * DM + tid] * val;
    __syncthreads();

    // amp = relu(vec . amp_w + amp_b)
    rv[tid] = vec[tid] * amp_w[tid];
    __syncthreads();
    for (int off = 64; off; off >>= 1) {
        if (tid < off) rv[tid] += rv[tid + off];
        __syncthreads();
    }
    if (tid == 0) amp_s = fmaxf(rv[0] + amp_b[0], 0.f);
    __syncthreads();

    const float4* vp = (const float4*)vec;

    // pos argmax over 512 (first max wins)
    float bv = -FLT_MAX; int bi = 1 << 30;
#pragma unroll
    for (int q = 0; q < 4; q++) {
        int o = q * 128 + tid;
        const float4* wp = (const float4*)(pos_w + (size_t)o * DM);
        float lg = pos_b[o];
#pragma unroll
        for (int i = 0; i < 32; i++) {
            float4 w4 = wp[i], v4 = vp[i];
            lg = fmaf(w4.x, v4.x, lg); lg = fmaf(w4.y, v4.y, lg);
            lg = fmaf(w4.z, v4.z, lg); lg = fmaf(w4.w, v4.w, lg);
        }
        if (lg > bv || (lg == bv && o < bi)) { bv = lg; bi = o; }
    }
    rv[tid] = bv; ri[tid] = bi;
    __syncthreads();
    for (int off = 64; off; off >>= 1) {
        if (tid < off) {
            float v2 = rv[tid + off]; int i2 = ri[tid + off];
            if (v2 > rv[tid] || (v2 == rv[tid] && i2 < ri[tid])) { rv[tid] = v2; ri[tid] = i2; }
        }
        __syncthreads();
    }
    if (tid == 0) jstar_s = ri[0];
    __syncthreads();

    // atom argmax over 256
    bv = -FLT_MAX; bi = 1 << 30;
#pragma unroll
    for (int q = 0; q < 2; q++) {
        int o = q * 128 + tid;
        const float4* wp = (const float4*)(atom_w + (size_t)o * DM);
        float lg = atom_b[o];
#pragma unroll
        for (int i = 0; i < 32; i++) {
            float4 w4 = wp[i], v4 = vp[i];
            lg = fmaf(w4.x, v4.x, lg); lg = fmaf(w4.y, v4.y, lg);
            lg = fmaf(w4.z, v4.z, lg); lg = fmaf(w4.w, v4.w, lg);
        }
        if (lg > bv || (lg == bv && o < bi)) { bv = lg; bi = o; }
    }
    rv[tid] = bv; ri[tid] = bi;
    __syncthreads();
    for (int off = 64; off; off >>= 1) {
        if (tid < off) {
            float v2 = rv[tid + off]; int i2 = ri[tid + off];
            if (v2 > rv[tid] || (v2 == rv[tid] && i2 < ri[tid])) { rv[tid] = v2; ri[tid] = i2; }
        }
        __syncthreads();
    }
    if (tid == 0) astar_s = ri[0];
    __syncthreads();

    float amp = amp_s;
    int p = jstar_s * 64;      // jnp.repeat(.,64): first max at 64*j*
    int a = astar_s;
    for (int i = tid; i < 256; i += 128) {
        int t = p + i;
        if (t < NS)
            atomicAdd(out + (size_t)b * NS + t, dmat[(size_t)a * 256 + i] * amp);
    }
}

// ---------------------------------------------------------------------------
extern "C" void kernel_launch(void* const* d_in, const int* in_sizes, int n_in,
                              void* d_out, int out_size)
{
    const float* x         = (const float*)d_in[0];
    const float* fb        = (const float*)d_in[1];
    const float* embed_w   = (const float*)d_in[2];
    const float* embed_b   = (const float*)d_in[3];
    const float* in_proj_w = (const float*)d_in[4];
    const float* in_proj_b = (const float*)d_in[5];
    const float* out_w     = (const float*)d_in[6];
    const float* out_b     = (const float*)d_in[7];
    const float* lin1_w    = (const float*)d_in[8];
    const float* lin1_b    = (const float*)d_in[9];
    const float* lin2_w    = (const float*)d_in[10];
    const float* lin2_b    = (const float*)d_in[11];
    const float* ln1_w     = (const float*)d_in[12];
    const float* ln1_b     = (const float*)d_in[13];
    const float* ln2_w     = (const float*)d_in[14];
    const float* ln2_b     = (const float*)d_in[15];
    const float* attn_w    = (const float*)d_in[16];
    const float* attn_b    = (const float*)d_in[17];
    const float* amp_w     = (const float*)d_in[18];
    const float* amp_b     = (const float*)d_in[19];
    const float* pos_w     = (const float*)d_in[20];
    const float* pos_b     = (const float*)d_in[21];
    const float* atom_w    = (const float*)d_in[22];
    const float* atom_b    = (const float*)d_in[23];
    const float* dmat      = (const float*)d_in[24];
    float* out = (float*)d_out;

    float *p_h, *p_qkv, *p_attno, *p_tmp, *p_ff;
    cudaGetSymbolAddress((void**)&p_h, g_h);
    cudaGetSymbolAddress((void**)&p_qkv, g_qkv);
    cudaGetSymbolAddress((void**)&p_attno, g_attno);
    cudaGetSymbolAddress((void**)&p_tmp, g_tmp);
    cudaGetSymbolAddress((void**)&p_ff, g_ff);

    cudaFuncSetAttribute(conv_pool_kernel, cudaFuncAttributeMaxDynamicSharedMemorySize, CONV_SMEM);
    conv_pool_kernel<<<dim3(128, 4, NB), 256, CONV_SMEM>>>(x, fb);
    embed_kernel<<<NB * NF, 128>>>(embed_w, embed_b);

    for (int i = 0; i < 6; i++) {
        linear_kernel<3, false><<<512, 128>>>(p_h, in_proj_w + (size_t)i * 384 * 128,
                                              in_proj_b + i * 384, p_qkv);
        attn_kernel<<<dim3(4, NB), 128>>>();
        linear_kernel<1, false><<<512, 128>>>(p_attno, out_w + (size_t)i * 128 * 128,
                                              out_b + i * 128, p_tmp);
        addln_kernel<<<NB * NF, 128>>>(p_h, p_tmp, ln1_w + i * 128, ln1_b + i * 128);
        linear_kernel<1, true><<<512, 128>>>(p_h, lin1_w + (size_t)i * 128 * 128,
                                             lin1_b + i * 128, p_ff);
        linear_kernel<1, false><<<512, 128>>>(p_ff, lin2_w + (size_t)i * 128 * 128,
                                              lin2_b + i * 128, p_tmp);
        addln_kernel<<<NB * NF, 128>>>(p_h, p_tmp, ln2_w + i * 128, ln2_b + i * 128);
    }

    topk_kernel<<<NB, 128>>>(attn_w, attn_b);
    cudaMemsetAsync(d_out, 0, (size_t)out_size * sizeof(float), 0);
    scatter_kernel<<<dim3(16, NB), 128>>>(amp_w, amp_b, pos_w, pos_b,
                                          atom_w, atom_b, dmat, out);
}